// round 11
// baseline (speedup 1.0000x reference)
#include <cuda_runtime.h>
#include <cuda_fp16.h>
#include <cstdint>

#define TDIM 1024
#define HDIM 2048
#define IDIM 5632
#define NEXP 8
#define TOPK 2
#define NROWS (TDIM * TOPK)       // 2048 routed rows
#define N1 (2 * IDIM)             // 11264 (gate+up)
#define BM 128
#define BN 128
#define BK 32
#define NSTAGE 3
#define MAXTILES 24
#define KSPLIT 2                  // GEMM2 split-K factor

#define ASTAGE 8192                         // A: 128 rows x 32 fp16, interleaved
#define BSTAGE 8192                         // B: fp16 chunks (both ks per 16B)
#define STAGE_BYTES (ASTAGE + BSTAGE)       // 16384

// ---------------- scratch (device globals: no allocations allowed) ----------
__device__ int    g_row_token[NROWS];
__device__ float  g_row_weight[NROWS];
__device__ int    g_row_slot[NROWS];
__device__ int    g_tile_expert[MAXTILES];
__device__ int    g_tile_rowstart[MAXTILES];
__device__ int    g_tile_rowcnt[MAXTILES];
__device__ int    g_ntiles;
// tile-padded, M-interleaved, k-relabeled fp16 A buffers
__device__ __half g_ax[(size_t)MAXTILES * 128 * HDIM];        // 12.6 MB
__device__ __half g_act_h[(size_t)MAXTILES * 128 * IDIM];     // 34.6 MB
__device__ float  g_partial[(size_t)KSPLIT * NROWS * HDIM];   // 32 MB

// byte offset of element (local row r, k within 32-wide kt block) in the
// interleaved A block. k relabeling pi: positions (2t,2t+1,2t+8,2t+9) hold
// original k (4t,4t+1,4t+2,4t+3).
__device__ __forceinline__ uint32_t ilv_off(int r, int kin)
{
    int ks = kin >> 4, kk = kin & 15;
    return (uint32_t)(ks * 4096 + (r >> 4) * 512 + (r & 7) * 64
         + (kk >> 2) * 16 + (((kk >> 1) & 1) * 2 + ((r >> 3) & 1)) * 4
         + (kk & 1) * 2);
}

// ---------------- routing ---------------------------------------------------
__global__ void route_kernel(const int* __restrict__ ids, const float* __restrict__ w)
{
    __shared__ int cnt[NEXP];
    __shared__ int off[NEXP];
    __shared__ int cur[NEXP];
    int tid = threadIdx.x;
    if (tid < NEXP) cnt[tid] = 0;
    __syncthreads();
    for (int a = tid; a < NROWS; a += blockDim.x)
        atomicAdd(&cnt[ids[a]], 1);
    __syncthreads();
    if (tid == 0) {
        int s = 0;
        for (int e = 0; e < NEXP; e++) { off[e] = s; cur[e] = s; s += cnt[e]; }
        int nt = 0;
        for (int e = 0; e < NEXP; e++) {
            for (int r = 0; r < cnt[e]; r += BM) {
                g_tile_expert[nt]   = e;
                g_tile_rowstart[nt] = off[e] + r;
                g_tile_rowcnt[nt]   = min(BM, cnt[e] - r);
                nt++;
            }
        }
        g_ntiles = nt;
    }
    __syncthreads();
    for (int a = tid; a < NROWS; a += blockDim.x) {
        int e = ids[a];
        int pos = atomicAdd(&cur[e], 1);
        g_row_token[pos]  = a / TOPK;
        g_row_weight[pos] = w[a];
        g_row_slot[pos]   = a;      // t*TOPK + k
    }
}

// ---------------- gather hidden -> tile-padded interleaved fp16 -------------
__global__ void gather_kernel(const float* __restrict__ src)
{
    const int tile = blockIdx.x;
    if (tile >= g_ntiles) return;
    const int r      = blockIdx.y;
    const int rowcnt = g_tile_rowcnt[tile];
    const int re     = r < rowcnt ? r : rowcnt - 1;
    const int token  = g_row_token[g_tile_rowstart[tile] + re];
    const float* srow = src + (size_t)token * HDIM;
    char* dbase = (char*)g_ax + (size_t)tile * (128 * HDIM * 2);
    const int tid = threadIdx.x;
    const int hb  = (r >> 3) & 1;
#pragma unroll
    for (int j = 0; j < 4; j++) {
        int pg  = tid + j * 256;
        int k16 = pg >> 3, p = pg & 7;
        float2 v = *(const float2*)(srow + k16 * 16 + p * 2);
        uint32_t off = (uint32_t)((k16 >> 1) * 8192 + (k16 & 1) * 4096
                     + (r >> 4) * 512 + (r & 7) * 64
                     + (p >> 1) * 16 + ((p & 1) * 2 + hb) * 4);
        *(__half2*)(dbase + off) = __floats2half2_rn(v.x, v.y);
    }
}

// ---------------- helpers ----------------------------------------------------
__device__ __forceinline__ uint32_t smem_u32(const void* p)
{
    uint32_t a;
    asm("{ .reg .u64 t; cvta.to.shared.u64 t, %1; cvt.u32.u64 %0, t; }"
        : "=r"(a) : "l"(p));
    return a;
}

__device__ __forceinline__ uint32_t packh2(float lo, float hi)
{
    uint32_t d;
    asm("cvt.rn.f16x2.f32 %0, %1, %2;" : "=r"(d) : "f"(hi), "f"(lo));
    return d;
}

#define CP_ASYNC16(dst, src) \
    asm volatile("cp.async.cg.shared.global [%0], [%1], 16;" :: "r"(dst), "l"(src) : "memory")
#define CP_COMMIT()  asm volatile("cp.async.commit_group;" ::: "memory")
#define CP_WAIT1()   asm volatile("cp.async.wait_group 1;" ::: "memory")

__device__ __forceinline__ void mma_f16(float (&d)[4],
                                        const uint32_t (&a)[4],
                                        uint32_t b0, uint32_t b1)
{
    asm volatile(
        "mma.sync.aligned.m16n8k16.row.col.f32.f16.f16.f32 "
        "{%0,%1,%2,%3}, {%4,%5,%6,%7}, {%8,%9}, {%0,%1,%2,%3};\n"
        : "+f"(d[0]), "+f"(d[1]), "+f"(d[2]), "+f"(d[3])
        : "r"(a[0]), "r"(a[1]), "r"(a[2]), "r"(a[3]),
          "r"(b0), "r"(b1));
}

// ---------------- grouped GEMM (fp16 mma.sync, fp16 A+B in smem) ------------
// A: interleaved fp16 via cp.async (contiguous 8KB block per kt).
// B: f32 global -> fp16 smem via coalesced LDG.128 + packh2 + STS.128,
//    register-pipelined 2 k-tiles ahead. Chunk (col, t) @ [col*64 + t*16]:
//    { b0(ks0), b1(ks0), b0(ks1), b1(ks1) } -> consumer does 1 LDS.128 per nt
//    per kt, covering BOTH ks halves.
// G2=false (GEMM1 fused SwiGLU): B rows interleave w13 gate/up; writes act.
// G2=true  (GEMM2, split-K): z-block sums K/KSPLIT slab into its own partial.
template<int KDIM, bool G2>
__global__ void __launch_bounds__(256, 2)
moe_gemm_h(const float* __restrict__ Bsrc)
{
    const int tile = blockIdx.x;
    if (tile >= g_ntiles) return;
    const int e        = g_tile_expert[tile];
    const int rowstart = g_tile_rowstart[tile];
    const int rowcnt   = g_tile_rowcnt[tile];
    const int nbase    = blockIdx.y * (G2 ? BN : 64);
    const int KLOC     = G2 ? KDIM / KSPLIT : KDIM;
    const int kbase    = G2 ? blockIdx.z * KLOC : 0;

    extern __shared__ uint32_t dsm[];
    const uint32_t smbase = smem_u32(dsm);
    const uint32_t base   = (smbase + 127u) & ~127u;
    char* dynb            = (char*)dsm + (base - smbase);

    const int tid  = threadIdx.x;
    const int lane = tid & 31;
    const int warp = tid >> 5;
    const int wm   = (warp & 1) * 64;
    const int wn   = (warp >> 1) * 32;
    const int g    = lane >> 2;
    const int tig  = lane & 3;

    // --- A staging source (cp.async block copy) -------------------------------
    const char* aBase = (G2 ? (const char*)g_act_h : (const char*)g_ax)
                      + (size_t)tile * (128 * (size_t)KDIM * 2)
                      + (size_t)kbase * 256;
    const uint32_t aDst0 = (uint32_t)(tid * 16);
    const uint32_t aDst1 = (uint32_t)(4096 + tid * 16);

    // --- B staging (coalesced LDG.128 -> packh2 -> STS.128) --------------------
    // thread owns chunks (col0 = tid>>2, t = tid&3) and (col0+64, t).
    const int col0 = tid >> 2;
    const int bt   = tid & 3;
    const int NTOT = G2 ? HDIM : N1;
    const float* Bexp = Bsrc + (size_t)e * NTOT * KDIM;
    const int row0 = G2 ? (nbase + col0)
                        : (((col0 & 1) ? IDIM : 0) + nbase + (col0 >> 1));
    const int col1 = col0 + 64;
    const int row1 = G2 ? (nbase + col1)
                        : (((col1 & 1) ? IDIM : 0) + nbase + (col1 >> 1));
    const float* bPtr0 = Bexp + (size_t)row0 * KDIM + kbase + bt * 4;
    const float* bPtr1 = Bexp + (size_t)row1 * KDIM + kbase + bt * 4;
    const uint32_t bDst0 = (uint32_t)(ASTAGE + tid * 16);         // col0*64+t*16
    const uint32_t bDst1 = (uint32_t)(ASTAGE + 4096 + tid * 16);  // col1

    float acc[4][4][4];
#pragma unroll
    for (int mt = 0; mt < 4; mt++)
#pragma unroll
        for (int nt = 0; nt < 4; nt++)
#pragma unroll
            for (int i = 0; i < 4; i++) acc[mt][nt][i] = 0.f;

    const int KITER = KLOC / BK;

    // --- prologue: fill stages 0,1 ---------------------------------------------
#pragma unroll
    for (int s = 0; s < 2; s++) {
        const uint32_t sb = base + s * STAGE_BYTES;
        CP_ASYNC16(sb + aDst0, aBase + s * 8192 + aDst0);
        CP_ASYNC16(sb + aDst1, aBase + s * 8192 + aDst1);
        CP_COMMIT();
        float4 q0 = *(const float4*)(bPtr0 + s * BK);        // col0, ks0
        float4 q1 = *(const float4*)(bPtr0 + s * BK + 16);   // col0, ks1
        float4 q2 = *(const float4*)(bPtr1 + s * BK);        // col1, ks0
        float4 q3 = *(const float4*)(bPtr1 + s * BK + 16);   // col1, ks1
        uint4 u0, u1;
        u0.x = packh2(q0.x, q0.y); u0.y = packh2(q0.z, q0.w);
        u0.z = packh2(q1.x, q1.y); u0.w = packh2(q1.z, q1.w);
        u1.x = packh2(q2.x, q2.y); u1.y = packh2(q2.z, q2.w);
        u1.z = packh2(q3.x, q3.y); u1.w = packh2(q3.z, q3.w);
        *(uint4*)(dynb + s * STAGE_BYTES + bDst0) = u0;
        *(uint4*)(dynb + s * STAGE_BYTES + bDst1) = u1;
    }
    CP_WAIT1();            // stage 0 A arrived (B stored synchronously)
    __syncthreads();

    // fragment base offsets (within stage)
    const uint32_t aFB = (uint32_t)((wm >> 4) * 512 + g * 64 + tig * 16);
    const uint32_t bFB = (uint32_t)(ASTAGE + (wn + g) * 64 + tig * 16);

    int buf = 0, nxt = 2;
    for (int kt = 0; kt < KITER; kt++) {
        const bool pre = (kt + 2 < KITER);
        float4 q0, q1, q2, q3;
        if (pre) {
            const uint32_t sb = base + nxt * STAGE_BYTES;
            CP_ASYNC16(sb + aDst0, aBase + (size_t)(kt + 2) * 8192 + aDst0);
            CP_ASYNC16(sb + aDst1, aBase + (size_t)(kt + 2) * 8192 + aDst1);
            const float* b0 = bPtr0 + (size_t)(kt + 2) * BK;
            const float* b1 = bPtr1 + (size_t)(kt + 2) * BK;
            q0 = *(const float4*)(b0);
            q1 = *(const float4*)(b0 + 16);
            q2 = *(const float4*)(b1);
            q3 = *(const float4*)(b1 + 16);
        }
        CP_COMMIT();

        char* sbuf = dynb + buf * STAGE_BYTES;
        // B fragments: one LDS.128 per nt covers both ks halves
        uint4 bq[4];
#pragma unroll
        for (int nt = 0; nt < 4; nt++)
            bq[nt] = *(const uint4*)(sbuf + bFB + nt * 512);
#pragma unroll
        for (int ks = 0; ks < 2; ks++) {
            const char* ab = sbuf + aFB + ks * 4096;
#pragma unroll
            for (int mt = 0; mt < 4; mt++) {
                uint4 av = *(const uint4*)(ab + mt * 512);
                uint32_t af[4] = { av.x, av.y, av.z, av.w };
                if (ks == 0) {
                    mma_f16(acc[mt][0], af, bq[0].x, bq[0].y);
                    mma_f16(acc[mt][1], af, bq[1].x, bq[1].y);
                    mma_f16(acc[mt][2], af, bq[2].x, bq[2].y);
                    mma_f16(acc[mt][3], af, bq[3].x, bq[3].y);
                } else {
                    mma_f16(acc[mt][0], af, bq[0].z, bq[0].w);
                    mma_f16(acc[mt][1], af, bq[1].z, bq[1].w);
                    mma_f16(acc[mt][2], af, bq[2].z, bq[2].w);
                    mma_f16(acc[mt][3], af, bq[3].z, bq[3].w);
                }
            }
        }

        if (pre) {
            char* db = dynb + nxt * STAGE_BYTES;
            uint4 u0, u1;
            u0.x = packh2(q0.x, q0.y); u0.y = packh2(q0.z, q0.w);
            u0.z = packh2(q1.x, q1.y); u0.w = packh2(q1.z, q1.w);
            u1.x = packh2(q2.x, q2.y); u1.y = packh2(q2.z, q2.w);
            u1.z = packh2(q3.x, q3.y); u1.w = packh2(q3.z, q3.w);
            *(uint4*)(db + bDst0) = u0;
            *(uint4*)(db + bDst1) = u1;
        }

        CP_WAIT1();
        __syncthreads();
        buf = buf == NSTAGE - 1 ? 0 : buf + 1;
        nxt = nxt == NSTAGE - 1 ? 0 : nxt + 1;
    }

    // --- epilogue ----------------------------------------------------------------
    char* actTile = (char*)g_act_h + (size_t)tile * (128 * (size_t)IDIM * 2);
#pragma unroll
    for (int mt = 0; mt < 4; mt++) {
        int r0e = wm + mt * 16 + g;
#pragma unroll
        for (int half = 0; half < 2; half++) {
            int r = r0e + half * 8;
            if (r < rowcnt) {
                int gr = rowstart + r;
                if (G2) {
                    size_t cbase = (size_t)blockIdx.z * ((size_t)NROWS * HDIM)
                                 + (size_t)g_row_slot[gr] * HDIM + nbase;
                    float  wgt   = g_row_weight[gr];
#pragma unroll
                    for (int nt = 0; nt < 4; nt++) {
                        int c = wn + nt * 8 + 2 * tig;
                        float2 v;
                        v.x = acc[mt][nt][half * 2 + 0] * wgt;
                        v.y = acc[mt][nt][half * 2 + 1] * wgt;
                        *(float2*)&g_partial[cbase + c] = v;
                    }
                } else {
                    // fused SwiGLU -> act in interleaved tile-padded layout
#pragma unroll
                    for (int nt = 0; nt < 4; nt++) {
                        float x = acc[mt][nt][half * 2 + 0];
                        float u = acc[mt][nt][half * 2 + 1];
                        float a = (x / (1.f + __expf(-x))) * u;
                        int aj = nbase + (wn >> 1) + nt * 4 + tig;
                        uint32_t off = (uint32_t)((aj >> 5) * 8192)
                                     + ilv_off(r, aj & 31);
                        *(__half*)(actTile + off) = __float2half_rn(a);
                    }
                }
            }
        }
    }
}

// ---------------- combine (atomic-free, deterministic) ----------------------
__global__ void combine_kernel(float* __restrict__ out)
{
    size_t idx = (size_t)blockIdx.x * blockDim.x + threadIdx.x;   // T*H
    size_t t = idx / HDIM;
    const size_t SP = (size_t)NROWS * HDIM;
    size_t b0 = idx + t * HDIM;          // slot 2t
    float s = g_partial[b0] + g_partial[b0 + HDIM]
            + g_partial[SP + b0] + g_partial[SP + b0 + HDIM];
    out[idx] = s;
}

// ---------------- launch -----------------------------------------------------
extern "C" void kernel_launch(void* const* d_in, const int* in_sizes, int n_in,
                              void* d_out, int out_size)
{
    const float* hidden = (const float*)d_in[0];
    const int*   ids    = (const int*)d_in[1];
    const float* wts    = (const float*)d_in[2];
    // d_in[3] = router_logits (unused)
    const float* w13    = (const float*)d_in[4];
    const float* w2     = (const float*)d_in[5];
    float* out = (float*)d_out;

    const int smem_bytes = 128 + NSTAGE * STAGE_BYTES;   // 49280
    cudaFuncSetAttribute(moe_gemm_h<HDIM, false>,
                         cudaFuncAttributeMaxDynamicSharedMemorySize, smem_bytes);
    cudaFuncSetAttribute(moe_gemm_h<IDIM, true>,
                         cudaFuncAttributeMaxDynamicSharedMemorySize, smem_bytes);

    route_kernel<<<1, 256>>>(ids, wts);
    gather_kernel<<<dim3(MAXTILES, 128), 256>>>(hidden);

    // GEMM1 (fused SwiGLU): each y-block produces 64 act columns
    moe_gemm_h<HDIM, false>
        <<<dim3(MAXTILES, IDIM / 64), 256, smem_bytes>>>(w13);

    // GEMM2: split-K=2 over z for wave balance
    moe_gemm_h<IDIM, true>
        <<<dim3(MAXTILES, HDIM / BN, KSPLIT), 256, smem_bytes>>>(w2);

    combine_kernel<<<(int)(((size_t)TDIM * HDIM) / 256), 256>>>(out);
}

// round 12
// speedup vs baseline: 1.4947x; 1.4947x over previous
#include <cuda_runtime.h>
#include <cuda_fp16.h>
#include <cstdint>

#define TDIM 1024
#define HDIM 2048
#define IDIM 5632
#define NEXP 8
#define TOPK 2
#define NROWS (TDIM * TOPK)       // 2048 routed rows
#define N1 (2 * IDIM)             // 11264 (gate+up)
#define BM 128
#define BN 128
#define BK 32
#define NSTAGE 4
#define MAXTILES 24
#define KSPLIT 2                  // GEMM2 split-K factor

#define ASTAGE 8192                         // A: 128 rows x 32 fp16, interleaved
#define BSTAGE 16384                        // B: 128 rows x 128B f32, XOR-swizzled
#define STAGE_BYTES (ASTAGE + BSTAGE)       // 24576

// ---------------- scratch (device globals: no allocations allowed) ----------
__device__ int    g_row_token[NROWS];
__device__ float  g_row_weight[NROWS];
__device__ int    g_row_slot[NROWS];
__device__ int    g_tile_expert[MAXTILES];
__device__ int    g_tile_rowstart[MAXTILES];
__device__ int    g_tile_rowcnt[MAXTILES];
__device__ int    g_ntiles;
// tile-padded, M-interleaved, k-relabeled fp16 A buffers
__device__ __half g_ax[(size_t)MAXTILES * 128 * HDIM];        // 12.6 MB
__device__ __half g_act_h[(size_t)MAXTILES * 128 * IDIM];     // 34.6 MB
__device__ float  g_partial[(size_t)KSPLIT * NROWS * HDIM];   // 32 MB

// byte offset of element (local row r, k within 32-wide kt block) in the
// interleaved A block. k relabeling pi: positions (2t,2t+1,2t+8,2t+9) hold
// original k (4t,4t+1,4t+2,4t+3).
__device__ __forceinline__ uint32_t ilv_off(int r, int kin)
{
    int ks = kin >> 4, kk = kin & 15;
    return (uint32_t)(ks * 4096 + (r >> 4) * 512 + (r & 7) * 64
         + (kk >> 2) * 16 + (((kk >> 1) & 1) * 2 + ((r >> 3) & 1)) * 4
         + (kk & 1) * 2);
}

// ---------------- routing ---------------------------------------------------
__global__ void route_kernel(const int* __restrict__ ids, const float* __restrict__ w)
{
    __shared__ int cnt[NEXP];
    __shared__ int off[NEXP];
    __shared__ int cur[NEXP];
    int tid = threadIdx.x;
    if (tid < NEXP) cnt[tid] = 0;
    __syncthreads();
    for (int a = tid; a < NROWS; a += blockDim.x)
        atomicAdd(&cnt[ids[a]], 1);
    __syncthreads();
    if (tid == 0) {
        int s = 0;
        for (int e = 0; e < NEXP; e++) { off[e] = s; cur[e] = s; s += cnt[e]; }
        int nt = 0;
        for (int e = 0; e < NEXP; e++) {
            for (int r = 0; r < cnt[e]; r += BM) {
                g_tile_expert[nt]   = e;
                g_tile_rowstart[nt] = off[e] + r;
                g_tile_rowcnt[nt]   = min(BM, cnt[e] - r);
                nt++;
            }
        }
        g_ntiles = nt;
    }
    __syncthreads();
    for (int a = tid; a < NROWS; a += blockDim.x) {
        int e = ids[a];
        int pos = atomicAdd(&cur[e], 1);
        g_row_token[pos]  = a / TOPK;
        g_row_weight[pos] = w[a];
        g_row_slot[pos]   = a;      // t*TOPK + k
    }
}

// ---------------- gather hidden -> tile-padded interleaved fp16 -------------
__global__ void gather_kernel(const float* __restrict__ src)
{
    const int tile = blockIdx.x;
    if (tile >= g_ntiles) return;
    const int r      = blockIdx.y;
    const int rowcnt = g_tile_rowcnt[tile];
    const int re     = r < rowcnt ? r : rowcnt - 1;
    const int token  = g_row_token[g_tile_rowstart[tile] + re];
    const float* srow = src + (size_t)token * HDIM;
    char* dbase = (char*)g_ax + (size_t)tile * (128 * HDIM * 2);
    const int tid = threadIdx.x;
    const int hb  = (r >> 3) & 1;
#pragma unroll
    for (int j = 0; j < 4; j++) {
        int pg  = tid + j * 256;
        int k16 = pg >> 3, p = pg & 7;
        float2 v = *(const float2*)(srow + k16 * 16 + p * 2);
        uint32_t off = (uint32_t)((k16 >> 1) * 8192 + (k16 & 1) * 4096
                     + (r >> 4) * 512 + (r & 7) * 64
                     + (p >> 1) * 16 + ((p & 1) * 2 + hb) * 4);
        *(__half2*)(dbase + off) = __floats2half2_rn(v.x, v.y);
    }
}

// ---------------- helpers ----------------------------------------------------
__device__ __forceinline__ uint32_t smem_u32(const void* p)
{
    uint32_t a;
    asm("{ .reg .u64 t; cvta.to.shared.u64 t, %1; cvt.u32.u64 %0, t; }"
        : "=r"(a) : "l"(p));
    return a;
}

__device__ __forceinline__ uint32_t packh2(float lo, float hi)
{
    uint32_t d;
    asm("cvt.rn.f16x2.f32 %0, %1, %2;" : "=r"(d) : "f"(hi), "f"(lo));
    return d;
}

#define CP_ASYNC16(dst, src) \
    asm volatile("cp.async.cg.shared.global [%0], [%1], 16;" :: "r"(dst), "l"(src) : "memory")
#define CP_COMMIT()  asm volatile("cp.async.commit_group;" ::: "memory")
#define CP_WAIT2()   asm volatile("cp.async.wait_group 2;" ::: "memory")

__device__ __forceinline__ void mma_f16(float (&d)[4],
                                        const uint32_t (&a)[4],
                                        uint32_t b0, uint32_t b1)
{
    asm volatile(
        "mma.sync.aligned.m16n8k16.row.col.f32.f16.f16.f32 "
        "{%0,%1,%2,%3}, {%4,%5,%6,%7}, {%8,%9}, {%0,%1,%2,%3};\n"
        : "+f"(d[0]), "+f"(d[1]), "+f"(d[2]), "+f"(d[3])
        : "r"(a[0]), "r"(a[1]), "r"(a[2]), "r"(a[3]),
          "r"(b0), "r"(b1));
}

// ---------------- grouped GEMM (fp16 mma.sync + cp.async 4-stage) -----------
// A: interleaved fp16 via cp.async (one contiguous 8KB block per kt).
// B: f32 natural k-order via cp.async, XOR parity swizzle (no pad):
//    chunk grp of row stored at slot grp ^ ((row&1)<<2) -> store and LDS.128
//    consumer phases both conflict-free at 128B rows.
// G2=false (GEMM1 fused SwiGLU): B rows interleave w13 gate/up; writes act.
// G2=true  (GEMM2, split-K): z-block sums K/KSPLIT slab into its own partial.
template<int KDIM, bool G2>
__global__ void __launch_bounds__(256, 2)
moe_gemm_h(const float* __restrict__ Bsrc)
{
    const int tile = blockIdx.x;
    if (tile >= g_ntiles) return;
    const int e        = g_tile_expert[tile];
    const int rowstart = g_tile_rowstart[tile];
    const int rowcnt   = g_tile_rowcnt[tile];
    const int nbase    = blockIdx.y * (G2 ? BN : 64);
    const int KLOC     = G2 ? KDIM / KSPLIT : KDIM;
    const int kbase    = G2 ? blockIdx.z * KLOC : 0;

    extern __shared__ uint32_t dsm[];
    const uint32_t smbase = smem_u32(dsm);
    const uint32_t base   = (smbase + 127u) & ~127u;
    char* dynb            = (char*)dsm + (base - smbase);

    const int tid  = threadIdx.x;
    const int lane = tid & 31;
    const int warp = tid >> 5;
    const int wm   = (warp & 1) * 64;
    const int wn   = (warp >> 1) * 32;
    const int g    = lane >> 2;
    const int tig  = lane & 3;

    // --- A staging source (cp.async block copy) -------------------------------
    const char* aBase = (G2 ? (const char*)g_act_h : (const char*)g_ax)
                      + (size_t)tile * (128 * (size_t)KDIM * 2)
                      + (size_t)kbase * 256;
    const uint32_t aDst0 = (uint32_t)(tid * 16);
    const uint32_t aDst1 = (uint32_t)(4096 + tid * 16);

    // --- B staging (coalesced cp.async, natural k order, swizzled dst) --------
    const int     NTOT = G2 ? HDIM : N1;
    const float*  Bexp = Bsrc + (size_t)e * NTOT * KDIM;
    const float* bSrc[4]; uint32_t bOffDst[4];
#pragma unroll
    for (int i = 0; i < 4; i++) {
        int slot = tid + 256 * i;
        int row = slot >> 3, grp = slot & 7;
        int srcrow = G2 ? (nbase + row)
                        : ((row & 1) ? IDIM : 0) + nbase + (row >> 1);
        bSrc[i]    = Bexp + (size_t)srcrow * KDIM + kbase + grp * 4;
        bOffDst[i] = (uint32_t)(ASTAGE + row * 128
                   + ((grp ^ ((row & 1) << 2)) * 16));
    }

    float acc[4][4][4];
#pragma unroll
    for (int mt = 0; mt < 4; mt++)
#pragma unroll
        for (int nt = 0; nt < 4; nt++)
#pragma unroll
            for (int i = 0; i < 4; i++) acc[mt][nt][i] = 0.f;

    const int KITER = KLOC / BK;

    // --- prologue: issue stages 0,1,2 ------------------------------------------
#pragma unroll
    for (int s = 0; s < 3; s++) {
        const uint32_t sb = base + s * STAGE_BYTES;
        CP_ASYNC16(sb + aDst0, aBase + s * 8192 + aDst0);
        CP_ASYNC16(sb + aDst1, aBase + s * 8192 + aDst1);
#pragma unroll
        for (int i = 0; i < 4; i++)
            CP_ASYNC16(sb + bOffDst[i], bSrc[i] + s * BK);
        CP_COMMIT();
    }
    CP_WAIT2();            // stage 0 complete
    __syncthreads();

    // fragment base offsets (within stage)
    const uint32_t aFB  = (uint32_t)((wm >> 4) * 512 + g * 64 + tig * 16);
    const uint32_t bRow = (uint32_t)(ASTAGE + (wn + g) * 128);
    const uint32_t xorb = (uint32_t)(((wn + g) & 1) << 2);
    // per-ks chunk byte offsets within the row
    const uint32_t bOff0 = ((0 * 4 + (uint32_t)tig) ^ xorb) * 16;
    const uint32_t bOff1 = ((1 * 4 + (uint32_t)tig) ^ xorb) * 16;

    int buf = 0, nxt = 3;
    for (int kt = 0; kt < KITER; kt++) {
        if (kt + 3 < KITER) {
            const uint32_t sb = base + nxt * STAGE_BYTES;
            CP_ASYNC16(sb + aDst0, aBase + (size_t)(kt + 3) * 8192 + aDst0);
            CP_ASYNC16(sb + aDst1, aBase + (size_t)(kt + 3) * 8192 + aDst1);
#pragma unroll
            for (int i = 0; i < 4; i++)
                CP_ASYNC16(sb + bOffDst[i], bSrc[i] + (kt + 3) * BK);
        }
        CP_COMMIT();

        char* sbuf = dynb + buf * STAGE_BYTES;
#pragma unroll
        for (int ks = 0; ks < 2; ks++) {
            const char* ab = sbuf + aFB + ks * 4096;
            const char* bb = sbuf + bRow + (ks ? bOff1 : bOff0);
            uint32_t bf[4][2];
#pragma unroll
            for (int nt = 0; nt < 4; nt++) {
                float4 v = *(const float4*)(bb + nt * 1024);   // 8 rows * 128B
                bf[nt][0] = packh2(v.x, v.y);   // positions 2tig, 2tig+1
                bf[nt][1] = packh2(v.z, v.w);   // positions 2tig+8, 2tig+9
            }
#pragma unroll
            for (int mt = 0; mt < 4; mt++) {
                uint4 av = *(const uint4*)(ab + mt * 512);
                uint32_t af[4] = { av.x, av.y, av.z, av.w };
                mma_f16(acc[mt][0], af, bf[0][0], bf[0][1]);
                mma_f16(acc[mt][1], af, bf[1][0], bf[1][1]);
                mma_f16(acc[mt][2], af, bf[2][0], bf[2][1]);
                mma_f16(acc[mt][3], af, bf[3][0], bf[3][1]);
            }
        }

        CP_WAIT2();
        __syncthreads();
        buf = buf == NSTAGE - 1 ? 0 : buf + 1;
        nxt = nxt == NSTAGE - 1 ? 0 : nxt + 1;
    }

    // --- epilogue ----------------------------------------------------------------
    char* actTile = (char*)g_act_h + (size_t)tile * (128 * (size_t)IDIM * 2);
#pragma unroll
    for (int mt = 0; mt < 4; mt++) {
        int r0e = wm + mt * 16 + g;
#pragma unroll
        for (int half = 0; half < 2; half++) {
            int r = r0e + half * 8;
            if (r < rowcnt) {
                int gr = rowstart + r;
                if (G2) {
                    size_t cbase = (size_t)blockIdx.z * ((size_t)NROWS * HDIM)
                                 + (size_t)g_row_slot[gr] * HDIM + nbase;
                    float  wgt   = g_row_weight[gr];
#pragma unroll
                    for (int nt = 0; nt < 4; nt++) {
                        int c = wn + nt * 8 + 2 * tig;
                        float2 v;
                        v.x = acc[mt][nt][half * 2 + 0] * wgt;
                        v.y = acc[mt][nt][half * 2 + 1] * wgt;
                        *(float2*)&g_partial[cbase + c] = v;
                    }
                } else {
                    // fused SwiGLU -> act in interleaved tile-padded layout
#pragma unroll
                    for (int nt = 0; nt < 4; nt++) {
                        float x = acc[mt][nt][half * 2 + 0];
                        float u = acc[mt][nt][half * 2 + 1];
                        float a = (x / (1.f + __expf(-x))) * u;
                        int aj = nbase + (wn >> 1) + nt * 4 + tig;
                        uint32_t off = (uint32_t)((aj >> 5) * 8192)
                                     + ilv_off(r, aj & 31);
                        *(__half*)(actTile + off) = __float2half_rn(a);
                    }
                }
            }
        }
    }
}

// ---------------- combine (atomic-free, deterministic) ----------------------
__global__ void combine_kernel(float* __restrict__ out)
{
    size_t idx = (size_t)blockIdx.x * blockDim.x + threadIdx.x;   // T*H
    size_t t = idx / HDIM;
    const size_t SP = (size_t)NROWS * HDIM;
    size_t b0 = idx + t * HDIM;          // slot 2t
    float s = g_partial[b0] + g_partial[b0 + HDIM]
            + g_partial[SP + b0] + g_partial[SP + b0 + HDIM];
    out[idx] = s;
}

// ---------------- launch -----------------------------------------------------
extern "C" void kernel_launch(void* const* d_in, const int* in_sizes, int n_in,
                              void* d_out, int out_size)
{
    const float* hidden = (const float*)d_in[0];
    const int*   ids    = (const int*)d_in[1];
    const float* wts    = (const float*)d_in[2];
    // d_in[3] = router_logits (unused)
    const float* w13    = (const float*)d_in[4];
    const float* w2     = (const float*)d_in[5];
    float* out = (float*)d_out;

    const int smem_bytes = 128 + NSTAGE * STAGE_BYTES;   // 98432
    cudaFuncSetAttribute(moe_gemm_h<HDIM, false>,
                         cudaFuncAttributeMaxDynamicSharedMemorySize, smem_bytes);
    cudaFuncSetAttribute(moe_gemm_h<IDIM, true>,
                         cudaFuncAttributeMaxDynamicSharedMemorySize, smem_bytes);

    route_kernel<<<1, 256>>>(ids, wts);
    gather_kernel<<<dim3(MAXTILES, 128), 256>>>(hidden);

    // GEMM1 (fused SwiGLU): each y-block produces 64 act columns
    moe_gemm_h<HDIM, false>
        <<<dim3(MAXTILES, IDIM / 64), 256, smem_bytes>>>(w13);

    // GEMM2: split-K=2 over z for wave balance
    moe_gemm_h<IDIM, true>
        <<<dim3(MAXTILES, HDIM / BN, KSPLIT), 256, smem_bytes>>>(w2);

    combine_kernel<<<(int)(((size_t)TDIM * HDIM) / 256), 256>>>(out);
}